// round 10
// baseline (speedup 1.0000x reference)
#include <cuda_runtime.h>
#include <math.h>

#define PH 7
#define PW 7
#define C  256
#define C2 (C / 2)
#define MAXN 1024

// Scratch (device globals; no allocation allowed)
__device__ int    g_slvl[MAXN];        // sorted levels
__device__ float4 g_pytab[MAXN * 8];   // per (roi,py): {ly, y0off_f2, y1off_f2, vy}
__device__ float4 g_pxtab[MAXN * 8];   // per (roi,px): {lx, x0off_f2, x1off_f2, vx}

// ---------------------------------------------------------------------------
// Kernel 1: level + stable counting sort + per-(roi,py)/(roi,px) sample tables.
// Offsets stored in float2 units so kernel 2 does pure IADD+LDG.
// Single block, 1024 threads, N <= 1024.
// ---------------------------------------------------------------------------
__global__ void level_sort_kernel(const float* __restrict__ rois, int N) {
    __shared__ unsigned long long warp_tot[32];
    int i    = threadIdx.x;
    int lane = i & 31;
    int wid  = i >> 5;

    int lvl = 0;
    float ybase = 0.f, ystep = 0.f, xbase = 0.f, xstep = 0.f;
    unsigned long long v = 0ULL;

    if (i < N) {
        float y1 = rois[i * 4 + 0];
        float x1 = rois[i * 4 + 1];
        float y2 = rois[i * 4 + 2];
        float x2 = rois[i * 4 + 3];
        float h = y2 - y1;
        float w = x2 - x1;
        // match reference fp32 path: log(sqrt(h*w))/log(2) - 5, round-half-even
        float lf = logf(sqrtf(h * w)) * (1.0f / logf(2.0f)) - 5.0f;
        int l = (int)rintf(lf);
        l = min(max(l, 0), 3);
        lvl = l;
        const float inv = 1.0f / 1024.0f;
        float ny1 = y1 * inv, nx1 = x1 * inv, ny2 = y2 * inv, nx2 = x2 * inv;
        float Hm1 = (float)((256 >> l) - 1);
        float Wm1 = Hm1;
        ybase = ny1 * Hm1;
        ystep = (ny2 - ny1) * Hm1 * (1.0f / (PH - 1));
        xbase = nx1 * Wm1;
        xstep = (nx2 - nx1) * Wm1 * (1.0f / (PW - 1));
        v = 1ULL << (16 * lvl);
    }

    // warp inclusive scan (64-bit)
    unsigned long long incl = v;
#pragma unroll
    for (int off = 1; off < 32; off <<= 1) {
        unsigned long long t = __shfl_up_sync(0xFFFFFFFFu, incl, off);
        if (lane >= off) incl += t;
    }
    if (lane == 31) warp_tot[wid] = incl;
    __syncthreads();

    if (wid == 0) {
        unsigned long long wt = warp_tot[lane];
#pragma unroll
        for (int off = 1; off < 32; off <<= 1) {
            unsigned long long t = __shfl_up_sync(0xFFFFFFFFu, wt, off);
            if (lane >= off) wt += t;
        }
        warp_tot[lane] = wt;
    }
    __syncthreads();

    unsigned long long total = warp_tot[31];
    unsigned long long offset = (wid > 0) ? warp_tot[wid - 1] : 0ULL;
    incl += offset;

    if (i < N) {
        int rank = (int)((incl >> (16 * lvl)) & 0xFFFFULL) - 1;
        int base = 0;
#pragma unroll
        for (int l = 0; l < 4; l++)
            if (l < lvl) base += (int)((total >> (16 * l)) & 0xFFFFULL);
        int pos = base + rank;
        g_slvl[pos] = lvl;

        int W = 256 >> lvl;
        float Wm1 = (float)(W - 1);

#pragma unroll
        for (int py = 0; py < PH; py++) {
            float iy = ybase + (float)py * ystep;
            float y0f = floorf(iy);
            float ly = iy - y0f;
            int y0 = min(max((int)y0f, 0), W - 1);
            int y1i = min(max((int)y0f + 1, 0), W - 1);
            float vy = ((iy >= 0.0f) && (iy <= Wm1)) ? 1.0f : 0.0f;
            float4 e;
            e.x = ly;
            e.y = __int_as_float(y0 * W * C2);   // row offset in float2 units
            e.z = __int_as_float(y1i * W * C2);
            e.w = vy;
            g_pytab[pos * 8 + py] = e;
        }
#pragma unroll
        for (int px = 0; px < PW; px++) {
            float ix = xbase + (float)px * xstep;
            float x0f = floorf(ix);
            float lx = ix - x0f;
            int x0 = min(max((int)x0f, 0), W - 1);
            int x1i = min(max((int)x0f + 1, 0), W - 1);
            float vx = ((ix >= 0.0f) && (ix <= Wm1)) ? 1.0f : 0.0f;
            float4 e;
            e.x = lx;
            e.y = __int_as_float(x0 * C2);       // col offset in float2 units
            e.z = __int_as_float(x1i * C2);
            e.w = vx;
            g_pxtab[pos * 8 + px] = e;
        }
    }
}

// ---------------------------------------------------------------------------
// Kernel 2: bilinear gather, float2 loads + precomputed tables.
// grid = (N, PH); block = 128 (thread = channel pair).
// Per px: 4 IADD + 4 LDG.64 + 12 FFMA (lerp form, matches reference) +
// mask-mul + 1 STG.64. Full px unroll -> 28 loads in flight per thread.
// LDG.64 = 2 L1 wavefronts/instr (vs float4's 4 at replay rate) at only 2x
// float4's instruction count -> balances L1 data path vs issue/LSU dispatch.
// ---------------------------------------------------------------------------
__global__ void __launch_bounds__(128, 6)
roi_align_kernel(const float* __restrict__ f0,
                 const float* __restrict__ f1,
                 const float* __restrict__ f2,
                 const float* __restrict__ f3,
                 float* __restrict__ out) {
    int roi = blockIdx.x;
    int py  = blockIdx.y;
    int c2  = threadIdx.x;   // 0..127 channel pair

    int lvl = g_slvl[roi];
    const float* f = (lvl == 0) ? f0 : (lvl == 1) ? f1 : (lvl == 2) ? f2 : f3;

    float4 pyt = g_pytab[roi * 8 + py];
    float ly = pyt.x;
    int y0e = __float_as_int(pyt.y);
    int y1e = __float_as_int(pyt.z);
    float vy = pyt.w;

    const float2* fb   = (const float2*)f;
    const float2* row0 = fb + y0e + c2;
    const float2* row1 = fb + y1e + c2;
    float2* o = (float2*)out + ((size_t)(roi * PH + py) * PW) * C2 + c2;

    // prologue: pull px tables into registers (uniform broadcast loads)
    float4 t[PW];
#pragma unroll
    for (int px = 0; px < PW; px++) t[px] = g_pxtab[roi * 8 + px];

#pragma unroll
    for (int px = 0; px < PW; px++) {
        float lx = t[px].x;
        int x0 = __float_as_int(t[px].y);
        int x1 = __float_as_int(t[px].z);
        float m = t[px].w * vy;   // 0 or 1

        float2 f00 = __ldg(row0 + x0);
        float2 f01 = __ldg(row0 + x1);
        float2 f10 = __ldg(row1 + x0);
        float2 f11 = __ldg(row1 + x1);

        // lerp form (same op order as reference)
        float top, bot;
        float2 r;
        top = fmaf(f01.x - f00.x, lx, f00.x);
        bot = fmaf(f11.x - f10.x, lx, f10.x);
        r.x = fmaf(bot - top, ly, top) * m;
        top = fmaf(f01.y - f00.y, lx, f00.y);
        bot = fmaf(f11.y - f10.y, lx, f10.y);
        r.y = fmaf(bot - top, ly, top) * m;

        __stcs(o + px * C2, r);
    }
}

extern "C" void kernel_launch(void* const* d_in, const int* in_sizes, int n_in,
                              void* d_out, int out_size) {
    const float* f0   = (const float*)d_in[0];
    const float* f1   = (const float*)d_in[1];
    const float* f2   = (const float*)d_in[2];
    const float* f3   = (const float*)d_in[3];
    const float* rois = (const float*)d_in[4];
    float* out = (float*)d_out;

    int N = in_sizes[4] / 4;
    if (N > MAXN) N = MAXN;

    level_sort_kernel<<<1, 1024>>>(rois, N);

    dim3 grid(N, PH);
    roi_align_kernel<<<grid, 128>>>(f0, f1, f2, f3, out);
}

// round 12
// speedup vs baseline: 1.5649x; 1.5649x over previous
#include <cuda_runtime.h>
#include <math.h>

#define PH 7
#define PW 7
#define C  256
#define C2 (C / 2)
#define MAXN 1024

// Scratch (device globals; no allocation allowed)
__device__ float4 g_scoord[MAXN];  // per-sorted-roi (ybase, ystep, xbase, xstep) in feature coords
__device__ int    g_slvl[MAXN];    // sorted levels

// ---------------------------------------------------------------------------
// Kernel 1: per-roi level + coordinate bases, stable counting sort.
// Packed 4x16-bit counters in uint64; warp-shuffle inclusive scan + warp-total
// combine. Single block, 1024 threads, N <= 1024.  (R8's light version.)
// ---------------------------------------------------------------------------
__global__ void level_sort_kernel(const float* __restrict__ rois, int N) {
    __shared__ unsigned long long warp_tot[32];
    int i    = threadIdx.x;
    int lane = i & 31;
    int wid  = i >> 5;

    int lvl = 0;
    float4 cb = make_float4(0.f, 0.f, 0.f, 0.f);
    unsigned long long v = 0ULL;

    if (i < N) {
        float y1 = rois[i * 4 + 0];
        float x1 = rois[i * 4 + 1];
        float y2 = rois[i * 4 + 2];
        float x2 = rois[i * 4 + 3];
        float h = y2 - y1;
        float w = x2 - x1;
        // match reference fp32 path: log(sqrt(h*w))/log(2) - 5, round-half-even
        float lf = logf(sqrtf(h * w)) * (1.0f / logf(2.0f)) - 5.0f;
        int l = (int)rintf(lf);
        l = min(max(l, 0), 3);
        lvl = l;
        const float inv = 1.0f / 1024.0f;
        float ny1 = y1 * inv, nx1 = x1 * inv, ny2 = y2 * inv, nx2 = x2 * inv;
        float Hm1 = (float)((256 >> l) - 1);
        float Wm1 = Hm1;
        cb.x = ny1 * Hm1;                              // ybase
        cb.y = (ny2 - ny1) * Hm1 * (1.0f / (PH - 1));  // ystep
        cb.z = nx1 * Wm1;                              // xbase
        cb.w = (nx2 - nx1) * Wm1 * (1.0f / (PW - 1));  // xstep
        v = 1ULL << (16 * lvl);
    }

    // warp inclusive scan (64-bit)
    unsigned long long incl = v;
#pragma unroll
    for (int off = 1; off < 32; off <<= 1) {
        unsigned long long t = __shfl_up_sync(0xFFFFFFFFu, incl, off);
        if (lane >= off) incl += t;
    }
    if (lane == 31) warp_tot[wid] = incl;
    __syncthreads();

    if (wid == 0) {
        unsigned long long wt = warp_tot[lane];
#pragma unroll
        for (int off = 1; off < 32; off <<= 1) {
            unsigned long long t = __shfl_up_sync(0xFFFFFFFFu, wt, off);
            if (lane >= off) wt += t;
        }
        warp_tot[lane] = wt;
    }
    __syncthreads();

    unsigned long long total = warp_tot[31];
    unsigned long long offset = (wid > 0) ? warp_tot[wid - 1] : 0ULL;
    incl += offset;

    if (i < N) {
        int rank = (int)((incl >> (16 * lvl)) & 0xFFFFULL) - 1;
        int base = 0;
#pragma unroll
        for (int l = 0; l < 4; l++)
            if (l < lvl) base += (int)((total >> (16 * l)) & 0xFFFFULL);
        int pos = base + rank;
        g_slvl[pos] = lvl;
        g_scoord[pos] = cb;
    }
}

// ---------------------------------------------------------------------------
// Kernel 2: bilinear gather, float2 loads with CONSECUTIVE-LANE layout.
// grid = (N, PH); block = 128 (thread = channel pair, lanes contiguous).
// Each warp-LDG.64 covers 256B contiguous = 2 L1 wavefronts (drain ~3.07 cyc)
// vs LDG.128's 4 wf (~7.2 cyc) -> ~26% fewer L1 read cycles per block.
// Full px unroll (28 float2 = 56 regs in flight), x recomputed per px (no
// register-hungry table prologue — R10's failure), weight-form bilinear,
// streaming stores. launch_bounds(128,5) keeps ~102 regs for the load front.
// ---------------------------------------------------------------------------
__global__ void __launch_bounds__(128, 5)
roi_align_kernel(const float* __restrict__ f0,
                 const float* __restrict__ f1,
                 const float* __restrict__ f2,
                 const float* __restrict__ f3,
                 float* __restrict__ out) {
    int roi = blockIdx.x;
    int py  = blockIdx.y;
    int c2  = threadIdx.x;   // 0..127 channel pair

    float4 cb = g_scoord[roi];
    int lvl = g_slvl[roi];

    const float* f = (lvl == 0) ? f0 : (lvl == 1) ? f1 : (lvl == 2) ? f2 : f3;
    int W = 256 >> lvl;
    float Wm1 = (float)(W - 1);

    float iy = cb.x + (float)py * cb.y;
    float y0f = floorf(iy);
    float ly = iy - y0f;
    int y0 = min(max((int)y0f, 0), W - 1);
    int y1 = min(max((int)y0f + 1, 0), W - 1);
    bool vy = (iy >= 0.0f) && (iy <= Wm1);
    float omly = 1.0f - ly;

    const float2* fb   = (const float2*)f;
    const float2* row0 = fb + (size_t)y0 * W * C2 + c2;
    const float2* row1 = fb + (size_t)y1 * W * C2 + c2;
    float2* o = (float2*)out + ((size_t)(roi * PH + py) * PW) * C2 + c2;

#pragma unroll
    for (int px = 0; px < PW; px++) {
        float ix = cb.z + (float)px * cb.w;
        float x0f = floorf(ix);
        float lx = ix - x0f;
        int x0 = min(max((int)x0f, 0), W - 1);
        int x1 = min(max((int)x0f + 1, 0), W - 1);
        bool vx = (ix >= 0.0f) && (ix <= Wm1);

        float2 f00 = __ldg(row0 + x0 * C2);
        float2 f01 = __ldg(row0 + x1 * C2);
        float2 f10 = __ldg(row1 + x0 * C2);
        float2 f11 = __ldg(row1 + x1 * C2);

        float omlx = 1.0f - lx;
        float w00 = omlx * omly;
        float w01 = lx * omly;
        float w10 = omlx * ly;
        float w11 = lx * ly;

        float2 r;
        r.x = fmaf(f11.x, w11, fmaf(f10.x, w10, fmaf(f01.x, w01, f00.x * w00)));
        r.y = fmaf(f11.y, w11, fmaf(f10.y, w10, fmaf(f01.y, w01, f00.y * w00)));

        if (!(vy && vx)) r = make_float2(0.f, 0.f);
        __stcs(o + px * C2, r);
    }
}

extern "C" void kernel_launch(void* const* d_in, const int* in_sizes, int n_in,
                              void* d_out, int out_size) {
    const float* f0   = (const float*)d_in[0];
    const float* f1   = (const float*)d_in[1];
    const float* f2   = (const float*)d_in[2];
    const float* f3   = (const float*)d_in[3];
    const float* rois = (const float*)d_in[4];
    float* out = (float*)d_out;

    int N = in_sizes[4] / 4;
    if (N > MAXN) N = MAXN;

    level_sort_kernel<<<1, 1024>>>(rois, N);

    dim3 grid(N, PH);
    roi_align_kernel<<<grid, 128>>>(f0, f1, f2, f3, out);
}